// round 8
// baseline (speedup 1.0000x reference)
#include <cuda_runtime.h>
#include <math.h>

#define NN 50000
#define NE 800000
#define DF 128

// ---------------- device scratch (no allocations allowed) ----------------
__device__ int   g_deg_col[NN];
__device__ int   g_cnt_row[NN];
__device__ int   g_offsets[NN + 1];
__device__ int   g_cursor[NN];
__device__ float g_dis[NN];
__device__ int   g_sorted_col[NE];
__device__ float g_sm[NN * DF];
__device__ float g_partial_max[512];
__device__ float g_xmax;

// ---------------- kernels ----------------
__global__ void zero_kernel() {
    int i = blockIdx.x * blockDim.x + threadIdx.x;
    if (i < NN) { g_deg_col[i] = 0; g_cnt_row[i] = 0; }
}

__global__ void hist_kernel(const int* __restrict__ ei) {
    int e = blockIdx.x * blockDim.x + threadIdx.x;
    if (e < NE) {
        int r = ei[e];        // row
        int c = ei[NE + e];   // col
        if ((unsigned)r < NN) atomicAdd(&g_cnt_row[r], 1);
        if ((unsigned)c < NN) atomicAdd(&g_deg_col[c], 1);
    }
}

// single block, 1024 threads: exclusive scan of cnt_row -> offsets/cursor,
// plus deg_inv_sqrt.
__global__ void scan_kernel() {
    __shared__ int sdata[1024];
    __shared__ int carry;
    if (threadIdx.x == 0) carry = 0;
    __syncthreads();
    for (int base = 0; base < NN; base += 1024) {
        int i = base + threadIdx.x;
        int v = (i < NN) ? g_cnt_row[i] : 0;
        sdata[threadIdx.x] = v;
        __syncthreads();
        for (int off = 1; off < 1024; off <<= 1) {
            int t = (threadIdx.x >= off) ? sdata[threadIdx.x - off] : 0;
            __syncthreads();
            sdata[threadIdx.x] += t;
            __syncthreads();
        }
        if (i < NN) {
            int excl = carry + sdata[threadIdx.x] - v;
            g_offsets[i] = excl;
            g_cursor[i]  = excl;
            int dc = g_deg_col[i];
            g_dis[i] = (dc > 0) ? rsqrtf((float)dc) : 0.0f;
        }
        __syncthreads();
        if (threadIdx.x == 0) carry += sdata[1023];
        __syncthreads();
    }
    if (threadIdx.x == 0) g_offsets[NN] = carry;
}

__global__ void scatter_kernel(const int* __restrict__ ei) {
    int e = blockIdx.x * blockDim.x + threadIdx.x;
    if (e < NE) {
        int r = ei[e];
        int c = ei[NE + e];
        if ((unsigned)r < NN && (unsigned)c < NN) {
            int pos = atomicAdd(&g_cursor[r], 1);
            if ((unsigned)pos < NE) g_sorted_col[pos] = c;
        }
    }
}

__global__ void max_part_kernel(const float* __restrict__ x, int n) {
    float m = -INFINITY;
    for (int i = blockIdx.x * blockDim.x + threadIdx.x; i < n;
         i += gridDim.x * blockDim.x)
        m = fmaxf(m, x[i]);
    #pragma unroll
    for (int o = 16; o > 0; o >>= 1) m = fmaxf(m, __shfl_xor_sync(~0u, m, o));
    __shared__ float s[32];
    if ((threadIdx.x & 31) == 0) s[threadIdx.x >> 5] = m;
    __syncthreads();
    if (threadIdx.x < 32) {
        m = (threadIdx.x < (blockDim.x >> 5)) ? s[threadIdx.x] : -INFINITY;
        #pragma unroll
        for (int o = 16; o > 0; o >>= 1) m = fmaxf(m, __shfl_xor_sync(~0u, m, o));
        if (threadIdx.x == 0) g_partial_max[blockIdx.x] = m;
    }
}

__global__ void max_final_kernel(int nb) {
    float m = (threadIdx.x < nb) ? g_partial_max[threadIdx.x] : -INFINITY;
    #pragma unroll
    for (int o = 16; o > 0; o >>= 1) m = fmaxf(m, __shfl_xor_sync(~0u, m, o));
    __shared__ float s[32];
    if ((threadIdx.x & 31) == 0) s[threadIdx.x >> 5] = m;
    __syncthreads();
    if (threadIdx.x < 32) {
        m = (threadIdx.x < (blockDim.x >> 5)) ? s[threadIdx.x] : -INFINITY;
        #pragma unroll
        for (int o = 16; o > 0; o >>= 1) m = fmaxf(m, __shfl_xor_sync(~0u, m, o));
        if (threadIdx.x == 0) g_xmax = m;
    }
}

__global__ void sm_kernel(const float* __restrict__ x,
                          const float* __restrict__ p, int n) {
    float pp = 2.0f / (1.0f + __expf(-p[0]));   // 2*sigmoid(p), > 0
    float M  = pp * g_xmax;                     // = max(pp*x) since pp>0
    int i = blockIdx.x * blockDim.x + threadIdx.x;
    if (i < n) g_sm[i] = __expf(fmaf(pp, x[i], -M));
}

// one warp per node; each lane owns 4 features (float4)
__global__ void agg_kernel(const float* __restrict__ x,
                           const float* __restrict__ eps,
                           float* __restrict__ out) {
    int warp = (blockIdx.x * blockDim.x + threadIdx.x) >> 5;
    int lane = threadIdx.x & 31;
    if (warp >= NN) return;
    int n = warp;
    int s = g_offsets[n];
    int e = g_offsets[n + 1];
    float dn = g_dis[n];

    const float4* __restrict__ x4  = (const float4*)x;
    const float4* __restrict__ sm4 = (const float4*)g_sm;

    float4 a1 = make_float4(0.f, 0.f, 0.f, 0.f);
    float4 a2 = make_float4(0.f, 0.f, 0.f, 0.f);

    for (int i = s; i < e; i++) {
        int c = g_sorted_col[i];      // broadcast load
        float w = dn * g_dis[c];
        float4 sv = sm4[c * 32 + lane];
        float4 xv = x4[c * 32 + lane];
        float ws;
        ws = w * sv.x; a1.x += ws; a2.x += ws * xv.x;
        ws = w * sv.y; a1.y += ws; a2.y += ws * xv.y;
        ws = w * sv.z; a1.z += ws; a2.z += ws * xv.z;
        ws = w * sv.w; a1.w += ws; a2.w += ws * xv.w;
    }

    float ep = 1.0f + eps[0];
    float4 xn = x4[n * 32 + lane];
    float4 o;
    o.x = a2.x / (a1.x + 1e-6f) + ep * xn.x;
    o.y = a2.y / (a1.y + 1e-6f) + ep * xn.y;
    o.z = a2.z / (a1.z + 1e-6f) + ep * xn.z;
    o.w = a2.w / (a1.w + 1e-6f) + ep * xn.w;
    ((float4*)out)[n * 32 + lane] = o;
}

// ---------------- launch ----------------
extern "C" void kernel_launch(void* const* d_in, const int* in_sizes, int n_in,
                              void* d_out, int out_size) {
    const float* x   = (const float*)d_in[0];
    const int*   ei  = (const int*)d_in[1];   // int32: JAX x64-disabled downcasts int64
    const float* eps = (const float*)d_in[2];
    const float* p   = (const float*)d_in[3];
    float* out = (float*)d_out;

    const int nfeat = NN * DF;

    zero_kernel<<<(NN + 255) / 256, 256>>>();
    hist_kernel<<<(NE + 255) / 256, 256>>>(ei);
    scan_kernel<<<1, 1024>>>();
    scatter_kernel<<<(NE + 255) / 256, 256>>>(ei);
    max_part_kernel<<<512, 256>>>(x, nfeat);
    max_final_kernel<<<1, 512>>>(512);
    sm_kernel<<<(nfeat + 255) / 256, 256>>>(x, p, nfeat);
    agg_kernel<<<(NN * 32 + 255) / 256, 256>>>(x, eps, out);
}

// round 11
// speedup vs baseline: 1.3053x; 1.3053x over previous
#include <cuda_runtime.h>
#include <cuda_fp16.h>
#include <math.h>

#define NN 50000
#define NE 800000
#define DF 128

// ---------------- device scratch (no allocations allowed) ----------------
__device__ int   g_deg_col[NN];
__device__ int   g_cnt_row[NN];
__device__ int   g_offsets[NN + 1];
__device__ int   g_cursor[NN];
__device__ float g_dis[NN];
__device__ int   g_sorted_col[NE];
__device__ __align__(16) __half2 g_pairs[NN * DF];   // {exp(pp*x), x} per feature
__device__ float g_partial_max[512];
__device__ float g_xmax;
__device__ float g_epsden;   // 1e-6 * exp(pp * xmax)

// ---------------- kernels ----------------
__global__ void zero_kernel() {
    int i = blockIdx.x * blockDim.x + threadIdx.x;
    if (i < NN) { g_deg_col[i] = 0; g_cnt_row[i] = 0; }
}

// 4 edges per thread, int4 loads for MLP
__global__ void hist_kernel(const int* __restrict__ ei) {
    int t = blockIdx.x * blockDim.x + threadIdx.x;
    if (t * 4 >= NE) return;
    int4 r4 = ((const int4*)ei)[t];
    int4 c4 = ((const int4*)(ei + NE))[t];
    int rr[4] = {r4.x, r4.y, r4.z, r4.w};
    int cc[4] = {c4.x, c4.y, c4.z, c4.w};
    #pragma unroll
    for (int k = 0; k < 4; k++) {
        if ((unsigned)rr[k] < NN) atomicAdd(&g_cnt_row[rr[k]], 1);
        if ((unsigned)cc[k] < NN) atomicAdd(&g_deg_col[cc[k]], 1);
    }
}

// single block, 1024 threads: warp-shuffle exclusive scan of cnt_row ->
// offsets/cursor, plus deg_inv_sqrt. 4 barriers per 1024-chunk.
__global__ void scan_kernel() {
    __shared__ int warpsums[32];
    __shared__ int carry_s;
    int tid = threadIdx.x, lane = tid & 31, wid = tid >> 5;
    if (tid == 0) carry_s = 0;
    __syncthreads();
    for (int base = 0; base < NN; base += 1024) {
        int i = base + tid;
        int v = (i < NN) ? g_cnt_row[i] : 0;
        int s = v;  // inclusive warp scan
        #pragma unroll
        for (int o = 1; o < 32; o <<= 1) {
            int t = __shfl_up_sync(~0u, s, o);
            if (lane >= o) s += t;
        }
        if (lane == 31) warpsums[wid] = s;
        __syncthreads();
        if (wid == 0) {
            int ws = warpsums[lane];
            #pragma unroll
            for (int o = 1; o < 32; o <<= 1) {
                int t = __shfl_up_sync(~0u, ws, o);
                if (lane >= o) ws += t;
            }
            warpsums[lane] = ws;
        }
        __syncthreads();
        int base_off = carry_s + (wid > 0 ? warpsums[wid - 1] : 0);
        int total = warpsums[31];
        if (i < NN) {
            int excl = base_off + s - v;
            g_offsets[i] = excl;
            g_cursor[i]  = excl;
            int dc = g_deg_col[i];
            g_dis[i] = (dc > 0) ? rsqrtf((float)dc) : 0.0f;
        }
        __syncthreads();
        if (tid == 0) carry_s += total;
        __syncthreads();
    }
    if (tid == 0) g_offsets[NN] = carry_s;
}

__global__ void scatter_kernel(const int* __restrict__ ei) {
    int t = blockIdx.x * blockDim.x + threadIdx.x;
    if (t * 4 >= NE) return;
    int4 r4 = ((const int4*)ei)[t];
    int4 c4 = ((const int4*)(ei + NE))[t];
    int rr[4] = {r4.x, r4.y, r4.z, r4.w};
    int cc[4] = {c4.x, c4.y, c4.z, c4.w};
    #pragma unroll
    for (int k = 0; k < 4; k++) {
        if ((unsigned)rr[k] < NN && (unsigned)cc[k] < NN) {
            int pos = atomicAdd(&g_cursor[rr[k]], 1);
            if ((unsigned)pos < NE) g_sorted_col[pos] = cc[k];
        }
    }
}

__global__ void max_part_kernel(const float* __restrict__ x, int n) {
    float m = -INFINITY;
    for (int i = blockIdx.x * blockDim.x + threadIdx.x; i < n;
         i += gridDim.x * blockDim.x)
        m = fmaxf(m, x[i]);
    #pragma unroll
    for (int o = 16; o > 0; o >>= 1) m = fmaxf(m, __shfl_xor_sync(~0u, m, o));
    __shared__ float s[32];
    if ((threadIdx.x & 31) == 0) s[threadIdx.x >> 5] = m;
    __syncthreads();
    if (threadIdx.x < 32) {
        m = (threadIdx.x < (blockDim.x >> 5)) ? s[threadIdx.x] : -INFINITY;
        #pragma unroll
        for (int o = 16; o > 0; o >>= 1) m = fmaxf(m, __shfl_xor_sync(~0u, m, o));
        if (threadIdx.x == 0) g_partial_max[blockIdx.x] = m;
    }
}

__global__ void max_final_kernel(const float* __restrict__ p, int nb) {
    float m = (threadIdx.x < nb) ? g_partial_max[threadIdx.x] : -INFINITY;
    #pragma unroll
    for (int o = 16; o > 0; o >>= 1) m = fmaxf(m, __shfl_xor_sync(~0u, m, o));
    __shared__ float s[32];
    if ((threadIdx.x & 31) == 0) s[threadIdx.x >> 5] = m;
    __syncthreads();
    if (threadIdx.x < 32) {
        m = (threadIdx.x < (blockDim.x >> 5)) ? s[threadIdx.x] : -INFINITY;
        #pragma unroll
        for (int o = 16; o > 0; o >>= 1) m = fmaxf(m, __shfl_xor_sync(~0u, m, o));
        if (threadIdx.x == 0) {
            g_xmax = m;
            float pp = 2.0f / (1.0f + __expf(-p[0]));
            g_epsden = 1e-6f * __expf(pp * m);   // ε scaled to the unshifted exp
        }
    }
}

// pack {exp(pp*x), x} as half2 per feature; 4 features per thread (float4 I/O)
__global__ void pair_kernel(const float* __restrict__ x,
                            const float* __restrict__ p, int n4) {
    int i = blockIdx.x * blockDim.x + threadIdx.x;
    if (i >= n4) return;
    float pp = 2.0f / (1.0f + __expf(-p[0]));
    float4 xv = ((const float4*)x)[i];
    __half2 h[4];
    h[0] = __floats2half2_rn(__expf(pp * xv.x), xv.x);
    h[1] = __floats2half2_rn(__expf(pp * xv.y), xv.y);
    h[2] = __floats2half2_rn(__expf(pp * xv.z), xv.z);
    h[3] = __floats2half2_rn(__expf(pp * xv.w), xv.w);
    ((float4*)g_pairs)[i] = *(float4*)h;
}

// one warp per node; each lane owns 4 features (one 16B pair load per edge)
__global__ void agg_kernel(const float* __restrict__ x,
                           const float* __restrict__ eps,
                           float* __restrict__ out) {
    int warp = (blockIdx.x * blockDim.x + threadIdx.x) >> 5;
    int lane = threadIdx.x & 31;
    if (warp >= NN) return;
    int n = warp;
    int s = g_offsets[n];
    int e = g_offsets[n + 1];
    float dn = g_dis[n];

    const float4* __restrict__ p4 = (const float4*)g_pairs;  // 32 float4 / row

    float a1[4] = {0.f, 0.f, 0.f, 0.f};
    float a2[4] = {0.f, 0.f, 0.f, 0.f};

    #pragma unroll 2
    for (int i = s; i < e; i++) {
        int c = g_sorted_col[i];          // broadcast load
        float w = dn * g_dis[c];
        float4 pv = p4[c * 32 + lane];
        const __half2* h = (const __half2*)&pv;
        #pragma unroll
        for (int j = 0; j < 4; j++) {
            float2 f = __half22float2(h[j]);   // {exp(pp*x), x}
            float ws = w * f.x;
            a1[j] += ws;
            a2[j] += ws * f.y;
        }
    }

    float ep = 1.0f + eps[0];
    float ed = g_epsden;
    float4 xn = ((const float4*)x)[n * 32 + lane];
    float4 o;
    o.x = a2[0] / (a1[0] + ed) + ep * xn.x;
    o.y = a2[1] / (a1[1] + ed) + ep * xn.y;
    o.z = a2[2] / (a1[2] + ed) + ep * xn.z;
    o.w = a2[3] / (a1[3] + ed) + ep * xn.w;
    ((float4*)out)[n * 32 + lane] = o;
}

// ---------------- launch ----------------
extern "C" void kernel_launch(void* const* d_in, const int* in_sizes, int n_in,
                              void* d_out, int out_size) {
    const float* x   = (const float*)d_in[0];
    const int*   ei  = (const int*)d_in[1];   // int32 (JAX x64 disabled)
    const float* eps = (const float*)d_in[2];
    const float* p   = (const float*)d_in[3];
    float* out = (float*)d_out;

    const int nfeat = NN * DF;
    const int n4    = nfeat / 4;

    zero_kernel<<<(NN + 255) / 256, 256>>>();
    hist_kernel<<<(NE / 4 + 255) / 256, 256>>>(ei);
    scan_kernel<<<1, 1024>>>();
    scatter_kernel<<<(NE / 4 + 255) / 256, 256>>>(ei);
    max_part_kernel<<<512, 256>>>(x, nfeat);
    max_final_kernel<<<1, 512>>>(p, 512);
    pair_kernel<<<(n4 + 255) / 256, 256>>>(x, p, n4);
    agg_kernel<<<(NN * 32 + 255) / 256, 256>>>(x, eps, out);
}